// round 14
// baseline (speedup 1.0000x reference)
#include <cuda_runtime.h>
#include <cuda_bf16.h>

// LIF spike scan: x [B=32, T=16, C=128, H=32, W=32] fp32 -> spikes (fp32, same shape).
// Per site: mem = mem*TAU + x_t; s = (mem >= THRESH); mem = (1-s)*mem.
//
// HBM-bound, 512 MiB irreducible 1:1 R/W traffic; 13 rounds plateau at
// 6.29-6.43 TB/s (GB300 practical mixed R/W HBM3e wall, ~80% of spec).
// R14 = R11 structure (two-stage pipelined loads, register scan, streaming
// loads) with the last unprobed cache-policy cell: __stwt write-through
// stores — spike lines stream to DRAM without L2 write-allocate, leaving L2
// sectors to inbound read fills.
// Traps: reg caps spill the deep batch (R7, -25%); block=512 (R6, -2%).

#define LIF_T      16
#define LIF_H      8               // half
#define LIF_THRESH 0.5f
#define LIF_TAU    0.25f
#define LIF_CHW4   32768           // C*H*W/4 = 128*32*32/4 (compile-time)

__device__ __forceinline__ float4 lif_step(float4& mem, float4 xin)
{
    mem.x = fmaf(mem.x, LIF_TAU, xin.x);
    mem.y = fmaf(mem.y, LIF_TAU, xin.y);
    mem.z = fmaf(mem.z, LIF_TAU, xin.z);
    mem.w = fmaf(mem.w, LIF_TAU, xin.w);

    float sx = (mem.x >= LIF_THRESH) ? 1.f : 0.f;
    float sy = (mem.y >= LIF_THRESH) ? 1.f : 0.f;
    float sz = (mem.z >= LIF_THRESH) ? 1.f : 0.f;
    float sw = (mem.w >= LIF_THRESH) ? 1.f : 0.f;

    mem.x = (sx != 0.f) ? 0.f : mem.x;
    mem.y = (sy != 0.f) ? 0.f : mem.y;
    mem.z = (sz != 0.f) ? 0.f : mem.z;
    mem.w = (sw != 0.f) ? 0.f : mem.w;

    return make_float4(sx, sy, sz, sw);
}

__global__ __launch_bounds__(256) void lif_spike_kernel(
    const float4* __restrict__ x,   // [B, T, CHW/4] viewed as float4
    float4* __restrict__ out)
{
    // gid in [0, B*CHW4) = [0, 1048576); all indices fit 32-bit.
    unsigned gid = blockIdx.x * blockDim.x + threadIdx.x;
    unsigned b   = gid >> 15;              // gid / LIF_CHW4
    unsigned sp  = gid & (LIF_CHW4 - 1);   // gid % LIF_CHW4

    unsigned base = b * (LIF_T * LIF_CHW4) + sp;   // max 2^24, fits 32-bit

    // Stage 0: loads for first half (streaming, evict-first)
    float4 va[LIF_H];
#pragma unroll
    for (int t = 0; t < LIF_H; t++) {
        va[t] = __ldcs(&x[base + t * LIF_CHW4]);
    }

    // Stage 1: issue second-half loads BEFORE first-half compute.
    float4 vb[LIF_H];
#pragma unroll
    for (int t = 0; t < LIF_H; t++) {
        vb[t] = __ldcs(&x[base + (LIF_H + t) * LIF_CHW4]);
    }

    // Compute + store half 1 (write-through; overlaps half-2 reads DRAM-side)
    float4 mem = make_float4(0.f, 0.f, 0.f, 0.f);
#pragma unroll
    for (int t = 0; t < LIF_H; t++) {
        float4 s = lif_step(mem, va[t]);
        __stwt(&out[base + t * LIF_CHW4], s);
    }

    // Compute + store half 2
#pragma unroll
    for (int t = 0; t < LIF_H; t++) {
        float4 s = lif_step(mem, vb[t]);
        __stwt(&out[base + (LIF_H + t) * LIF_CHW4], s);
    }
}

extern "C" void kernel_launch(void* const* d_in, const int* in_sizes, int n_in,
                              void* d_out, int out_size)
{
    const float* x = (const float*)d_in[0];
    float* out = (float*)d_out;

    // x: [32, 16, 128, 32, 32]; n_sites = 32 * 32768 = 1,048,576 float4 sites.
    const int chw  = 128 * 32 * 32;
    const int B    = in_sizes[0] / (LIF_T * chw);   // 32
    const int n_sites = B * LIF_CHW4;               // 1,048,576

    const int threads = 256;
    const int blocks = n_sites / threads;           // 4096, exact

    lif_spike_kernel<<<blocks, threads>>>((const float4*)x, (float4*)out);
}

// round 15
// speedup vs baseline: 1.0055x; 1.0055x over previous
#include <cuda_runtime.h>
#include <cuda_bf16.h>

// LIF spike scan: x [B=32, T=16, C=128, H=32, W=32] fp32 -> spikes (fp32, same shape).
// Per site: mem = mem*TAU + x_t; s = (mem >= THRESH); mem = (1-s)*mem.
//
// FINAL (R11 — best of 14 rounds: 81.98us best, 82.0-82.2 typical, ~6.4 TB/s, rel_err 0).
// HBM-bound, 512 MiB irreducible 1:1 R/W traffic. Fourteen rounds spanning
// occupancy 21-87%, per-warp MLP 2-16, all load/store cache operators
// (default/cs/wt), block 256/512, reg caps, index micro-opts, and R/W phasing
// all plateau at 6.29-6.43 TB/s — the GB300's practical mixed read/write
// HBM3e wall (~80% of 8 TB/s spec); inter-variant deltas below bench noise.
// Bandwidth on sm_103a is path-independent (LDG.cv ≡ TMA), so no access-
// pattern lever remains. Floor: 512 MiB / 6.4 TB/s ≈ 76us kernel + ~6us
// graph-replay overhead = 82us end-to-end.
//
// Structure (two-stage pipeline):
//  - one float4 per thread, perfectly coalesced (512B/warp/access)
//  - 16 independent streaming loads (__ldcs, evict-first; zero reuse),
//    second half issued before first-half compute so half-2 reads overlap
//    half-1 stores DRAM-side (interleaved mixed streams, fewer bus turnarounds)
//  - sequential LIF scan entirely in registers
//  - streaming stores (__stcs; __stwt tested worse in R14)
//  - compile-time shapes (div -> shift/mask), 32-bit indexing, exact grid
// Traps confirmed this session: reg caps spill the deep load batch (R7, -25%);
// block=512 costs concurrency (R6, -2%).

#define LIF_T      16
#define LIF_H      8               // half
#define LIF_THRESH 0.5f
#define LIF_TAU    0.25f
#define LIF_CHW4   32768           // C*H*W/4 = 128*32*32/4 (compile-time)

__device__ __forceinline__ float4 lif_step(float4& mem, float4 xin)
{
    mem.x = fmaf(mem.x, LIF_TAU, xin.x);
    mem.y = fmaf(mem.y, LIF_TAU, xin.y);
    mem.z = fmaf(mem.z, LIF_TAU, xin.z);
    mem.w = fmaf(mem.w, LIF_TAU, xin.w);

    float sx = (mem.x >= LIF_THRESH) ? 1.f : 0.f;
    float sy = (mem.y >= LIF_THRESH) ? 1.f : 0.f;
    float sz = (mem.z >= LIF_THRESH) ? 1.f : 0.f;
    float sw = (mem.w >= LIF_THRESH) ? 1.f : 0.f;

    mem.x = (sx != 0.f) ? 0.f : mem.x;
    mem.y = (sy != 0.f) ? 0.f : mem.y;
    mem.z = (sz != 0.f) ? 0.f : mem.z;
    mem.w = (sw != 0.f) ? 0.f : mem.w;

    return make_float4(sx, sy, sz, sw);
}

__global__ __launch_bounds__(256) void lif_spike_kernel(
    const float4* __restrict__ x,   // [B, T, CHW/4] viewed as float4
    float4* __restrict__ out)
{
    // gid in [0, B*CHW4) = [0, 1048576); all indices fit 32-bit.
    unsigned gid = blockIdx.x * blockDim.x + threadIdx.x;
    unsigned b   = gid >> 15;              // gid / LIF_CHW4
    unsigned sp  = gid & (LIF_CHW4 - 1);   // gid % LIF_CHW4

    unsigned base = b * (LIF_T * LIF_CHW4) + sp;   // max 2^24, fits 32-bit

    // Stage 0: loads for first half (streaming, evict-first)
    float4 va[LIF_H];
#pragma unroll
    for (int t = 0; t < LIF_H; t++) {
        va[t] = __ldcs(&x[base + t * LIF_CHW4]);
    }

    // Stage 1: issue second-half loads BEFORE first-half compute,
    // so they are in flight while half 1 computes/stores.
    float4 vb[LIF_H];
#pragma unroll
    for (int t = 0; t < LIF_H; t++) {
        vb[t] = __ldcs(&x[base + (LIF_H + t) * LIF_CHW4]);
    }

    // Compute + store half 1 (stores overlap with half-2 reads DRAM-side)
    float4 mem = make_float4(0.f, 0.f, 0.f, 0.f);
#pragma unroll
    for (int t = 0; t < LIF_H; t++) {
        float4 s = lif_step(mem, va[t]);
        __stcs(&out[base + t * LIF_CHW4], s);
    }

    // Compute + store half 2
#pragma unroll
    for (int t = 0; t < LIF_H; t++) {
        float4 s = lif_step(mem, vb[t]);
        __stcs(&out[base + (LIF_H + t) * LIF_CHW4], s);
    }
}

extern "C" void kernel_launch(void* const* d_in, const int* in_sizes, int n_in,
                              void* d_out, int out_size)
{
    const float* x = (const float*)d_in[0];
    float* out = (float*)d_out;

    // x: [32, 16, 128, 32, 32]; n_sites = 32 * 32768 = 1,048,576 float4 sites.
    const int chw  = 128 * 32 * 32;
    const int B    = in_sizes[0] / (LIF_T * chw);   // 32
    const int n_sites = B * LIF_CHW4;               // 1,048,576

    const int threads = 256;
    const int blocks = n_sites / threads;           // 4096, exact

    lif_spike_kernel<<<blocks, threads>>>((const float4*)x, (float4*)out);
}